// round 2
// baseline (speedup 1.0000x reference)
#include <cuda_runtime.h>
#include <cstdint>

#define D_DIM   512
#define N_HEADS 64
#define NJ      128   // N_HEADS * 2
#define BM      128
#define BK      16

// Scratch (no cudaMalloc allowed)
__device__ float g_Wt[D_DIM * NJ];      // W / sigma, transposed: [k][j]
__device__ float g_bias[NJ];
__device__ float g_partials[1024];      // per-block loss partials

// ---------------------------------------------------------------------------
// Packed fp32x2 helpers (Blackwell FFMA2 — 2x fp32 FMA throughput)
// ---------------------------------------------------------------------------
__device__ __forceinline__ unsigned long long dup_f32x2(float x) {
    unsigned long long r;
    asm("mov.b64 %0, {%1, %1};" : "=l"(r) : "f"(x));
    return r;
}
__device__ __forceinline__ unsigned long long fma_f32x2(unsigned long long a,
                                                        unsigned long long b,
                                                        unsigned long long c) {
    unsigned long long d;
    asm("fma.rn.f32x2 %0, %1, %2, %3;" : "=l"(d) : "l"(a), "l"(b), "l"(c));
    return d;
}

// ---------------------------------------------------------------------------
// Phase 1: spectral norm (1 power iteration) per head, fold 1/sigma into Wt.
// grid = 64 blocks (one per head), 128 threads.
// ---------------------------------------------------------------------------
__global__ void prep_kernel(const float* __restrict__ W,
                            const float* __restrict__ bias_in,
                            const float* __restrict__ u) {
    int n = blockIdx.x;
    int t = threadIdx.x;  // 0..127
    __shared__ float r0s[128];
    __shared__ float r1s[128];

    if (t == 0) {
        g_bias[2 * n]     = bias_in[2 * n];
        g_bias[2 * n + 1] = bias_in[2 * n + 1];
    }

    const float* Wn = W + (size_t)n * 2 * D_DIM;
    float u0 = u[2 * n], u1 = u[2 * n + 1];

    float w0[4], w1[4], vr[4];
    float s = 0.f;
#pragma unroll
    for (int i = 0; i < 4; i++) {
        int d = t + i * 128;
        w0[i] = Wn[d];
        w1[i] = Wn[D_DIM + d];
        vr[i] = w0[i] * u0 + w1[i] * u1;
        s += vr[i] * vr[i];
    }
    r0s[t] = s;
    __syncthreads();
    for (int off = 64; off > 0; off >>= 1) {
        if (t < off) r0s[t] += r0s[t + off];
        __syncthreads();
    }
    float vnorm = sqrtf(r0s[0]);
    float rn = 1.0f / fmaxf(vnorm, 1e-12f);
    __syncthreads();  // r0s reused below

    float t0 = 0.f, t1 = 0.f;
#pragma unroll
    for (int i = 0; i < 4; i++) {
        float v = vr[i] * rn;
        t0 += w0[i] * v;
        t1 += w1[i] * v;
    }
    r0s[t] = t0;
    r1s[t] = t1;
    __syncthreads();
    for (int off = 64; off > 0; off >>= 1) {
        if (t < off) { r0s[t] += r0s[t + off]; r1s[t] += r1s[t + off]; }
        __syncthreads();
    }
    float T0 = r0s[0], T1 = r1s[0];
    float nt = sqrtf(T0 * T0 + T1 * T1);
    float den = fmaxf(nt, 1e-12f);
    float uu0 = T0 / den, uu1 = T1 / den;
    float sigma = uu0 * T0 + uu1 * T1;
    float inv = 1.0f / sigma;

#pragma unroll
    for (int i = 0; i < 4; i++) {
        int d = t + i * 128;
        g_Wt[(size_t)d * NJ + 2 * n]     = w0[i] * inv;
        g_Wt[(size_t)d * NJ + 2 * n + 1] = w1[i] * inv;
    }
}

// ---------------------------------------------------------------------------
// Phase 2: GEMM (M=B, N=128, K=512) fp32 with FFMA2 + fused epilogue
// (pred store, argmax, log_softmax over the 64 heads, CE-loss partials).
// 256 threads, 8x8 micro-tile, BM=128, full N in one pass.
// ---------------------------------------------------------------------------
__global__ __launch_bounds__(256, 2)
void main_kernel(const float* __restrict__ A,
                 const int* __restrict__ target,
                 float* __restrict__ pred_out,   // may be null
                 float* __restrict__ arg_out,    // may be null
                 int B) {
    __shared__ float As[BK][BM + 4];
    __shared__ float Bs[BK][NJ];
    __shared__ float ls_red[16];

    int tid = threadIdx.x;
    int tx = tid & 15;
    int ty = tid >> 4;
    int r0 = blockIdx.x * BM;

    unsigned long long acc[8][4];
#pragma unroll
    for (int i = 0; i < 8; i++)
#pragma unroll
        for (int j = 0; j < 4; j++) acc[i][j] = 0ULL;

    for (int k0 = 0; k0 < D_DIM; k0 += BK) {
        // Load A tile 128x16 (coalesced float4, transposed store to As[k][m])
#pragma unroll
        for (int l = tid; l < 512; l += 256) {
            int row = l >> 2;
            int kq = l & 3;
            float4 av = *(const float4*)&A[(size_t)(r0 + row) * D_DIM + k0 + kq * 4];
            As[kq * 4 + 0][row] = av.x;
            As[kq * 4 + 1][row] = av.y;
            As[kq * 4 + 2][row] = av.z;
            As[kq * 4 + 3][row] = av.w;
        }
        // Load B tile 16x128 (already k-major in g_Wt)
#pragma unroll
        for (int l = tid; l < 512; l += 256) {
            int k = l >> 5;
            int j = (l & 31) * 4;
            *(float4*)&Bs[k][j] = *(const float4*)&g_Wt[(size_t)(k0 + k) * NJ + j];
        }
        __syncthreads();

#pragma unroll
        for (int kk = 0; kk < BK; kk++) {
            float4 a0 = *(const float4*)&As[kk][ty * 8];
            float4 a1 = *(const float4*)&As[kk][ty * 8 + 4];
            ulonglong2 bl0 = *(const ulonglong2*)&Bs[kk][tx * 8];
            ulonglong2 bl1 = *(const ulonglong2*)&Bs[kk][tx * 8 + 4];
            unsigned long long bp0 = bl0.x, bp1 = bl0.y, bp2 = bl1.x, bp3 = bl1.y;
            float av[8] = {a0.x, a0.y, a0.z, a0.w, a1.x, a1.y, a1.z, a1.w};
#pragma unroll
            for (int i = 0; i < 8; i++) {
                unsigned long long ap = dup_f32x2(av[i]);
                acc[i][0] = fma_f32x2(ap, bp0, acc[i][0]);
                acc[i][1] = fma_f32x2(ap, bp1, acc[i][1]);
                acc[i][2] = fma_f32x2(ap, bp2, acc[i][2]);
                acc[i][3] = fma_f32x2(ap, bp3, acc[i][3]);
            }
        }
        __syncthreads();
    }

    // ---------------- epilogue ----------------
    float bias_r[8];
    *(float4*)&bias_r[0] = *(const float4*)&g_bias[tx * 8];
    *(float4*)&bias_r[4] = *(const float4*)&g_bias[tx * 8 + 4];

    float loss_local = 0.f;

#pragma unroll
    for (int i = 0; i < 8; i++) {
        int r = r0 + ty * 8 + i;
        float c[8];
#pragma unroll
        for (int j = 0; j < 4; j++) {
            unsigned long long v = acc[i][j];
            c[2 * j]     = __uint_as_float((unsigned)(v & 0xffffffffULL)) + bias_r[2 * j];
            c[2 * j + 1] = __uint_as_float((unsigned)(v >> 32))           + bias_r[2 * j + 1];
        }
        if (pred_out) {
            float4 s0 = make_float4(c[0], c[1], c[2], c[3]);
            float4 s1 = make_float4(c[4], c[5], c[6], c[7]);
            *(float4*)&pred_out[(size_t)r * NJ + tx * 8]     = s0;
            *(float4*)&pred_out[(size_t)r * NJ + tx * 8 + 4] = s1;
        }
        int4 tg4 = *(const int4*)&target[(size_t)r * N_HEADS + tx * 4];
        if (arg_out) {
            float4 am = make_float4(c[1] > c[0] ? 1.f : 0.f,
                                    c[3] > c[2] ? 1.f : 0.f,
                                    c[5] > c[4] ? 1.f : 0.f,
                                    c[7] > c[6] ? 1.f : 0.f);
            *(float4*)&arg_out[(size_t)r * N_HEADS + tx * 4] = am;
        }

        // log_softmax over the head axis (64 heads) per class c in {0,1}:
        // each of the 16 tx-lanes of this row holds 4 heads (cols tx*8..tx*8+7).
        float m0 = fmaxf(fmaxf(c[0], c[2]), fmaxf(c[4], c[6]));
        float m1 = fmaxf(fmaxf(c[1], c[3]), fmaxf(c[5], c[7]));
#pragma unroll
        for (int off = 8; off; off >>= 1) {
            m0 = fmaxf(m0, __shfl_xor_sync(0xffffffffu, m0, off));
            m1 = fmaxf(m1, __shfl_xor_sync(0xffffffffu, m1, off));
        }
        float s0 = 0.f, s1 = 0.f, tsum = 0.f, cntf = 0.f;
        int tgv[4] = {tg4.x, tg4.y, tg4.z, tg4.w};
#pragma unroll
        for (int j = 0; j < 4; j++) {
            s0 += __expf(c[2 * j] - m0);
            s1 += __expf(c[2 * j + 1] - m1);
            tsum += tgv[j] ? c[2 * j + 1] : c[2 * j];
            cntf += (float)tgv[j];
        }
#pragma unroll
        for (int off = 8; off; off >>= 1) {
            s0   += __shfl_xor_sync(0xffffffffu, s0, off);
            s1   += __shfl_xor_sync(0xffffffffu, s1, off);
            tsum += __shfl_xor_sync(0xffffffffu, tsum, off);
            cntf += __shfl_xor_sync(0xffffffffu, cntf, off);
        }
        if (tx == 0) {
            float lse0 = m0 + __logf(s0);
            float lse1 = m1 + __logf(s1);
            // loss_row = cnt0*lse0 + cnt1*lse1 - sum_n pred[n, target[n]]
            loss_local += ((float)N_HEADS - cntf) * lse0 + cntf * lse1 - tsum;
        }
    }

    if (tx == 0) ls_red[ty] = loss_local;
    __syncthreads();
    if (tid == 0) {
        float s = 0.f;
#pragma unroll
        for (int k = 0; k < 16; k++) s += ls_red[k];
        g_partials[blockIdx.x] = s;
    }
}

// ---------------------------------------------------------------------------
// Phase 3: deterministic loss reduction
// ---------------------------------------------------------------------------
__global__ void finish_kernel(float* __restrict__ out_loss, int nB, int B) {
    __shared__ double sm[256];
    int t = threadIdx.x;
    double v = 0.0;
    for (int i = t; i < nB; i += 256) v += (double)g_partials[i];
    sm[t] = v;
    __syncthreads();
    for (int off = 128; off; off >>= 1) {
        if (t < off) sm[t] += sm[t + off];
        __syncthreads();
    }
    if (t == 0) *out_loss = (float)(sm[0] / (2.0 * (double)B));
}

// ---------------------------------------------------------------------------
extern "C" void kernel_launch(void* const* d_in, const int* in_sizes, int n_in,
                              void* d_out, int out_size) {
    const float* feature = (const float*)d_in[0];
    const int*   target  = (const int*)d_in[1];
    const float* W       = (const float*)d_in[2];
    const float* b       = (const float*)d_in[3];
    const float* u       = (const float*)d_in[4];

    int B = in_sizes[0] / D_DIM;           // 65536

    long long predN = (long long)B * NJ;       // B*128
    long long BN    = (long long)B * N_HEADS;  // B*64

    float* out = (float*)d_out;
    float* pred_out = nullptr;
    float* arg_out  = nullptr;
    long long off_loss = -1;

    if ((long long)out_size == predN + BN + 1) {
        pred_out = out; arg_out = out + predN; off_loss = predN + BN;
    } else if ((long long)out_size == predN) {
        pred_out = out;
    } else if ((long long)out_size == BN) {
        arg_out = out;
    } else if (out_size == 1) {
        off_loss = 0;
    } else {
        pred_out = out;
        if ((long long)out_size >= predN + BN)     arg_out  = out + predN;
        if ((long long)out_size >= predN + BN + 1) off_loss = predN + BN;
    }

    prep_kernel<<<N_HEADS, 128>>>(W, b, u);

    int nB = B / BM;  // 512
    main_kernel<<<nB, 256>>>(feature, target, pred_out, arg_out, B);

    if (off_loss >= 0) finish_kernel<<<1, 256>>>(out + off_loss, nB, B);
}